// round 13
// baseline (speedup 1.0000x reference)
#include <cuda_runtime.h>
#include <cstdint>

// Problem constants (N=32768, D=64, K=64 per reference)
#define NPTS 32768
#define DIM 64
#define NK 64
#define ROWS_PER_BLOCK 64
#define NTHREADS 64            // 2 warps, e-split: warp0 quarters {0,3}, warp1 {1,2}
#define NBLOCKS (NPTS / ROWS_PER_BLOCK)   // 512

// Scratch (allocation-free rule: __device__ globals)
__device__ __align__(16) float d_negmuP[NK * DIM];  // -(means_k @ P_k), [K,D]
__device__ float d_Cpart[NK];                       // C without stick-breaking cumsum
__device__ float d_sdb[NK];                         // digamma(b)-digamma(a+b)

// ---------------------------------------------------------------------------
// NaN-proof helpers (identity on valid inputs).
// ---------------------------------------------------------------------------
static __device__ __forceinline__ double safe_log(double v) {
    v = fabs(v);
    if (v < 1e-300) v = 1e-300;
    return log(v);
}

// digamma in double; recurrence as independent divides (bit-identical order).
static __device__ __forceinline__ double digamma_d(double x) {
    if (!(x > 1e-6)) x = 1e-6;
    double r = 0.0;
    const double m = (x < 6.0) ? ceil(6.0 - x) : 0.0;   // <= 6 for x >= 0.5
#pragma unroll
    for (int j = 0; j < 6; ++j)
        if ((double)j < m) r -= 1.0 / (x + (double)j);
    x += m;
    const double inv  = 1.0 / x;
    const double inv2 = inv * inv;
    const double s = inv2 * (1.0 / 12.0
                   - inv2 * (1.0 / 120.0
                   - inv2 * (1.0 / 252.0
                   - inv2 * (1.0 / 240.0))));
    return r + log(x) - 0.5 * inv - s;
}

// ---------------------------------------------------------------------------
// Prep: 64 blocks (cluster k) x 64 threads (dimension i).
// ---------------------------------------------------------------------------
__global__ void bgm_prep_a(const float* __restrict__ means,
                           const float* __restrict__ P,
                           const float* __restrict__ wc,
                           const float* __restrict__ v64a,
                           const float* __restrict__ v64b) {
    const int k = blockIdx.x;
    const int i = threadIdx.x;
    __shared__ double sd[NK];

    const bool a_is_dof = (v64a[0] > 32.0f);   // dof in [65,114], mp in (0.5,10]
    const float* __restrict__ dof = a_is_dof ? v64a : v64b;
    const float* __restrict__ mp  = a_is_dof ? v64b : v64a;

    const double dofk = (double)dof[k];

    const double t  = digamma_d(0.5 * (dofk - (double)i));
    const double lg = safe_log((double)P[k * DIM * DIM + i * DIM + i]);
    sd[i] = lg + 0.5 * t;
    __syncthreads();

    {   // negmuP column i
        float s = 0.0f;
        for (int d = 0; d < DIM; ++d)
            s = fmaf(means[k * DIM + d], P[k * DIM * DIM + d * DIM + i], s);
        d_negmuP[k * DIM + i] = -s;
    }

    for (int off = 32; off > 0; off >>= 1) {
        if (i < off) sd[i] += sd[i + off];
        __syncthreads();
    }

    if (i == 0) {
        double mpk = (double)mp[k];
        if (!(mpk > 1e-6)) mpk = 1e-6;
        const double a  = (double)wc[k];
        const double b  = (double)wc[NK + k];
        const double ds = digamma_d(a + b);
        const double dga = digamma_d(a);
        const double dgb = digamma_d(b);
        double C = sd[0]
                 + 0.5 * (double)DIM * 0.69314718055994530942   // +0.5*D*log2
                 - 0.5 * (double)DIM * 1.8378770664093454836    // -0.5*D*log(2pi)
                 - 0.5 * (double)DIM * safe_log(dofk)
                 - 0.5 * (double)DIM / mpk
                 + dga - ds;
        d_Cpart[k] = (float)C;
        d_sdb[k]   = (float)(dgb - ds);
    }
}

// ---------------------------------------------------------------------------
// Packed f32x2 helpers (FFMA2 SASS — 2x scalar FFMA throughput on sm_103a)
// ---------------------------------------------------------------------------
static __device__ __forceinline__ unsigned long long ff2(
    unsigned long long a, unsigned long long b, unsigned long long c) {
    unsigned long long d;
    asm("fma.rn.f32x2 %0, %1, %2, %3;" : "=l"(d) : "l"(a), "l"(b), "l"(c));
    return d;
}
static __device__ __forceinline__ unsigned long long fadd2(
    unsigned long long a, unsigned long long b) {
    unsigned long long d;
    asm("add.rn.f32x2 %0, %1, %2;" : "=l"(d) : "l"(a), "l"(b));
    return d;
}
static __device__ __forceinline__ unsigned long long pack2(float x) {
    unsigned long long d;
    asm("mov.b64 %0, {%1, %1};" : "=l"(d) : "f"(x));
    return d;
}
static __device__ __forceinline__ void unpack2(unsigned long long v, float& lo, float& hi) {
    asm("mov.b64 {%0, %1}, %2;" : "=f"(lo), "=f"(hi) : "l"(v));
}

// cp.async 16B helpers
static __device__ __forceinline__ void cp16(uint32_t smem_addr, const void* gptr) {
    asm volatile("cp.async.cg.shared.global [%0], [%1], 16;" :: "r"(smem_addr), "l"(gptr));
}
static __device__ __forceinline__ void cp_commit() {
    asm volatile("cp.async.commit_group;");
}
template <int N>
static __device__ __forceinline__ void cp_wait() {
    asm volatile("cp.async.wait_group %0;" :: "n"(N));
}

// ---------------------------------------------------------------------------
// Main kernel: 512 blocks x 64 threads (2 warps), 64 rows/block.
// e-SPLIT: thread t owns rows (t%32, t%32+32); warp0 computes e-quarters
// {0,3}, warp1 {1,2} (triangular d-counts 80 each — balanced).
// d-loop is SOFTWARE-PIPELINED: operands for d+1 are prefetched into
// registers before issuing d's FFMA2s (hides the ~29cyc LDS latency).
// The d+1==dmax overread lands in the pad after the P buffers (valid smem).
// Per-(row,k) sq = warp0 half + warp1 half, merged via a 1-k-deep pipelined
// smem exchange. Warp0 tracks argmax (strict >, first-max). OUTPUT: float32.
// ---------------------------------------------------------------------------
__global__ __launch_bounds__(NTHREADS) void bgm_argmax_kernel(
    const float* __restrict__ X,
    const float* __restrict__ P,
    float* __restrict__ out) {

    // Two 4096-float P buffers + 80-float pad (absorbs d+1==64 prefetch overread)
    __shared__ __align__(16) float PsmBuf[2 * DIM * DIM + 80];
    __shared__ __align__(16) float Xsm[ROWS_PER_BLOCK * (DIM + 1)];   // padded
    __shared__ float Csm[NK];
    __shared__ float Sdb[NK];
    __shared__ float sqPart[2][2][32];   // [kbuf][rowhalf][lane] — warp1's halves

    const int tid  = threadIdx.x;
    const int wid  = tid >> 5;
    const int lane = tid & 31;
    const int row0 = blockIdx.x * ROWS_PER_BLOCK;

    // Stage X tile: 64 rows -> 1024 float4, 16 per thread.
    {
        const float4* __restrict__ Xg =
            reinterpret_cast<const float4*>(X + row0 * DIM);
        for (int i = tid; i < ROWS_PER_BLOCK * (DIM / 4); i += NTHREADS) {
            const float4 v = Xg[i];
            const int r = i >> 4;
            const int c = (i & 15) << 2;
            float* dst = &Xsm[r * (DIM + 1) + c];
            dst[0] = v.x; dst[1] = v.y; dst[2] = v.z; dst[3] = v.w;
        }
    }
    Sdb[tid] = d_sdb[tid];           // NTHREADS == NK
    __syncthreads();
    {   // Stick-breaking exclusive cumsum, bit-identical sequential fp32 order.
        float pre = 0.0f;
        for (int j = 0; j < tid; ++j) pre += Sdb[j];
        Csm[tid] = d_Cpart[tid] + pre;
    }

    // Prologue: stage P_0 into buffer 0 (16 float4 per thread)
    {
        const float4* src = reinterpret_cast<const float4*>(P);
        const uint32_t dst = (uint32_t)__cvta_generic_to_shared(&PsmBuf[0]);
#pragma unroll
        for (int j = 0; j < 16; ++j)
            cp16(dst + (tid + j * NTHREADS) * 16, src + tid + j * NTHREADS);
        cp_commit();
    }

    // This warp's two e-quarters (d-work 80 each way: 16+64 vs 32+48).
    const int qA = (wid == 0) ? 0 : 1;
    const int qB = (wid == 0) ? 3 : 2;

    const int xb0 = lane * (DIM + 1);
    const int xb1 = (lane + 32) * (DIM + 1);
    float best0 = __int_as_float(0xff800000u), best1 = best0;
    int   arg0 = 0, arg1 = 0;
    float sqPrev0 = 0.0f, sqPrev1 = 0.0f;   // warp0's own halves for k-1

    const ulonglong2* __restrict__ nmAll =
        reinterpret_cast<const ulonglong2*>(d_negmuP);

    for (int k = 0; k < NK; ++k) {
        __syncthreads();   // (a) prev buffer free; warp1's k-1 partials visible
                           //     (also covers Xsm/Csm staging at k=0)

        // Warp0: merge halves for k-1 and update argmax.
        if (wid == 0 && k > 0) {
            const int pb = (k - 1) & 1;
            const float Ck = Csm[k - 1];
            const float s0 = sqPrev0 + sqPart[pb][0][lane];
            const float s1 = sqPrev1 + sqPart[pb][1][lane];
            const float w0 = fmaf(-0.5f, s0, Ck);
            const float w1 = fmaf(-0.5f, s1, Ck);
            if (w0 > best0) { best0 = w0; arg0 = k - 1; }
            if (w1 > best1) { best1 = w1; arg1 = k - 1; }
        }

        if (k + 1 < NK) {
            const float4* src = reinterpret_cast<const float4*>(P + (k + 1) * DIM * DIM);
            const uint32_t dst = (uint32_t)__cvta_generic_to_shared(
                &PsmBuf[((k + 1) & 1) * DIM * DIM]);
#pragma unroll
            for (int j = 0; j < 16; ++j)
                cp16(dst + (tid + j * NTHREADS) * 16, src + tid + j * NTHREADS);
            cp_commit();
            cp_wait<1>();   // P_k complete; P_{k+1} in flight
        } else {
            cp_wait<0>();
        }
        __syncthreads();    // (b) P_k visible to both warps

        const float* __restrict__ Pk = &PsmBuf[(k & 1) * DIM * DIM];
        unsigned long long s0 = 0ULL, s1 = 0ULL;   // running sq halves (f32x2)

#pragma unroll
        for (int h = 0; h < 2; ++h) {
            const int q    = (h == 0) ? qA : qB;
            const int dmax = 16 * (q + 1);         // triangular bound
            const ulonglong2* __restrict__ prQ =
                reinterpret_cast<const ulonglong2*>(Pk + (q << 4));
            // row stride in ulonglong2 units: 64 floats = 16

            unsigned long long a0[8], a1[8];
#pragma unroll
            for (int j = 0; j < 8; ++j) { a0[j] = 0ULL; a1[j] = 0ULL; }

            // Software pipeline: prefetch d=0 operands.
            ulonglong2 n0 = prQ[0], n1 = prQ[1], n2 = prQ[2], n3 = prQ[3];
            unsigned long long nx0 = pack2(Xsm[xb0]);
            unsigned long long nx1 = pack2(Xsm[xb1]);

#pragma unroll 4
            for (int d = 0; d < dmax; ++d) {
                const ulonglong2 c0 = n0, c1 = n1, c2 = n2, c3 = n3;
                const unsigned long long cx0 = nx0, cx1 = nx1;

                // Prefetch d+1 (overread at d+1==dmax is absorbed by pad / X bounds).
                const ulonglong2* __restrict__ pn = prQ + ((d + 1) << 4);
                n0 = pn[0]; n1 = pn[1]; n2 = pn[2]; n3 = pn[3];
                nx0 = pack2(Xsm[xb0 + d + 1]);
                nx1 = pack2(Xsm[xb1 + d + 1]);

                a0[0] = ff2(cx0, c0.x, a0[0]);
                a0[1] = ff2(cx0, c0.y, a0[1]);
                a0[2] = ff2(cx0, c1.x, a0[2]);
                a0[3] = ff2(cx0, c1.y, a0[3]);
                a0[4] = ff2(cx0, c2.x, a0[4]);
                a0[5] = ff2(cx0, c2.y, a0[5]);
                a0[6] = ff2(cx0, c3.x, a0[6]);
                a0[7] = ff2(cx0, c3.y, a0[7]);
                a1[0] = ff2(cx1, c0.x, a1[0]);
                a1[1] = ff2(cx1, c0.y, a1[1]);
                a1[2] = ff2(cx1, c1.x, a1[2]);
                a1[3] = ff2(cx1, c1.y, a1[3]);
                a1[4] = ff2(cx1, c2.x, a1[4]);
                a1[5] = ff2(cx1, c2.y, a1[5]);
                a1[6] = ff2(cx1, c3.x, a1[6]);
                a1[7] = ff2(cx1, c3.y, a1[7]);
            }

            // Quarter epilogue: s += (acc + negmuP_quarter)^2
            const ulonglong2* __restrict__ nm = nmAll + (k << 4) + (q << 2);
#pragma unroll
            for (int j = 0; j < 4; ++j) {
                const ulonglong2 m = nm[j];
                const unsigned long long e0a = fadd2(a0[2 * j],     m.x);
                const unsigned long long e0b = fadd2(a0[2 * j + 1], m.y);
                const unsigned long long e1a = fadd2(a1[2 * j],     m.x);
                const unsigned long long e1b = fadd2(a1[2 * j + 1], m.y);
                s0 = ff2(e0a, e0a, s0);
                s0 = ff2(e0b, e0b, s0);
                s1 = ff2(e1a, e1a, s1);
                s1 = ff2(e1b, e1b, s1);
            }
        }

        float l0, h0, l1, h1;
        unpack2(s0, l0, h0);
        unpack2(s1, l1, h1);
        const float half0 = l0 + h0;   // this warp's sq half, row lane
        const float half1 = l1 + h1;   // row lane+32

        if (wid == 1) {
            sqPart[k & 1][0][lane] = half0;
            sqPart[k & 1][1][lane] = half1;
        } else {
            sqPrev0 = half0;
            sqPrev1 = half1;
        }
    }

    __syncthreads();   // warp1's k=63 partials visible
    if (wid == 0) {
        const int pb = (NK - 1) & 1;
        const float Ck = Csm[NK - 1];
        const float s0 = sqPrev0 + sqPart[pb][0][lane];
        const float s1 = sqPrev1 + sqPart[pb][1][lane];
        const float w0 = fmaf(-0.5f, s0, Ck);
        const float w1 = fmaf(-0.5f, s1, Ck);
        if (w0 > best0) { best0 = w0; arg0 = NK - 1; }
        if (w1 > best1) { best1 = w1; arg1 = NK - 1; }
        out[row0 + lane]      = (float)arg0;
        out[row0 + lane + 32] = (float)arg1;
    }
}

// ---------------------------------------------------------------------------
// Launch. Inputs identified by ELEMENT COUNT; dof/mp disambiguated on device.
// Output: float32 index values [N].
// ---------------------------------------------------------------------------
extern "C" void kernel_launch(void* const* d_in, const int* in_sizes, int n_in,
                              void* d_out, int out_size) {
    (void)out_size;
    const float* X     = nullptr;
    const float* means = nullptr;
    const float* P     = nullptr;
    const float* wc    = nullptr;
    const float* v64a  = nullptr;
    const float* v64b  = nullptr;

    for (int i = 0; i < n_in; ++i) {
        const float* p = (const float*)d_in[i];
        switch (in_sizes[i]) {
            case 2097152: X = p; break;
            case 262144:  P = p; break;
            case 4096:    means = p; break;
            case 128:     wc = p; break;
            case 64:      if (!v64a) v64a = p; else v64b = p; break;
            default: break;
        }
    }
    if (!v64b) v64b = v64a;  // defensive
    float* out = (float*)d_out;

    bgm_prep_a<<<NK, DIM>>>(means, P, wc, v64a, v64b);
    bgm_argmax_kernel<<<NBLOCKS, NTHREADS>>>(X, P, out);
}

// round 14
// speedup vs baseline: 1.1117x; 1.1117x over previous
#include <cuda_runtime.h>
#include <cstdint>

// Problem constants (N=32768, D=64, K=64 per reference)
#define NPTS 32768
#define DIM 64
#define NK 64
#define RPT 4                       // rows per thread
#define NTHREADS 128                // 4 warps; warp w owns e-eighths {w, 7-w}
#define ROWS_PER_BLOCK 128          // 32 lanes * RPT
#define NBLOCKS (NPTS / ROWS_PER_BLOCK)   // 256

// Dynamic smem layout (floats)
#define SM_P    0                   // [2][4096] P double buffer
#define SM_X    8192                // [128][65] padded X tile
#define SM_C    (SM_X + 128 * 65)   // [64] per-cluster constants
#define SM_SDB  (SM_C + 64)         // [64] stick-breaking terms
#define SM_SQP  (SM_SDB + 64)       // [2][4][128] per-warp sq partials
#define SM_TOTF (SM_SQP + 2 * 4 * 128)
#define SMEM_BYTES (SM_TOTF * 4)

// Scratch (allocation-free rule: __device__ globals)
__device__ __align__(16) float d_negmuP[NK * DIM];  // -(means_k @ P_k), [K,D]
__device__ float d_Cpart[NK];
__device__ float d_sdb[NK];

// ---------------------------------------------------------------------------
static __device__ __forceinline__ double safe_log(double v) {
    v = fabs(v);
    if (v < 1e-300) v = 1e-300;
    return log(v);
}

static __device__ __forceinline__ double digamma_d(double x) {
    if (!(x > 1e-6)) x = 1e-6;
    double r = 0.0;
    const double m = (x < 6.0) ? ceil(6.0 - x) : 0.0;   // <= 6 for x >= 0.5
#pragma unroll
    for (int j = 0; j < 6; ++j)
        if ((double)j < m) r -= 1.0 / (x + (double)j);
    x += m;
    const double inv  = 1.0 / x;
    const double inv2 = inv * inv;
    const double s = inv2 * (1.0 / 12.0
                   - inv2 * (1.0 / 120.0
                   - inv2 * (1.0 / 252.0
                   - inv2 * (1.0 / 240.0))));
    return r + log(x) - 0.5 * inv - s;
}

// ---------------------------------------------------------------------------
// Prep: 64 blocks (cluster k) x 64 threads (dimension i).
// ---------------------------------------------------------------------------
__global__ void bgm_prep_a(const float* __restrict__ means,
                           const float* __restrict__ P,
                           const float* __restrict__ wc,
                           const float* __restrict__ v64a,
                           const float* __restrict__ v64b) {
    const int k = blockIdx.x;
    const int i = threadIdx.x;
    __shared__ double sd[NK];

    const bool a_is_dof = (v64a[0] > 32.0f);   // dof in [65,114], mp in (0.5,10]
    const float* __restrict__ dof = a_is_dof ? v64a : v64b;
    const float* __restrict__ mp  = a_is_dof ? v64b : v64a;

    const double dofk = (double)dof[k];

    const double t  = digamma_d(0.5 * (dofk - (double)i));
    const double lg = safe_log((double)P[k * DIM * DIM + i * DIM + i]);
    sd[i] = lg + 0.5 * t;
    __syncthreads();

    {   // negmuP column i
        float s = 0.0f;
        for (int d = 0; d < DIM; ++d)
            s = fmaf(means[k * DIM + d], P[k * DIM * DIM + d * DIM + i], s);
        d_negmuP[k * DIM + i] = -s;
    }

    for (int off = 32; off > 0; off >>= 1) {
        if (i < off) sd[i] += sd[i + off];
        __syncthreads();
    }

    if (i == 0) {
        double mpk = (double)mp[k];
        if (!(mpk > 1e-6)) mpk = 1e-6;
        const double a  = (double)wc[k];
        const double b  = (double)wc[NK + k];
        const double ds = digamma_d(a + b);
        const double dga = digamma_d(a);
        const double dgb = digamma_d(b);
        double C = sd[0]
                 + 0.5 * (double)DIM * 0.69314718055994530942
                 - 0.5 * (double)DIM * 1.8378770664093454836
                 - 0.5 * (double)DIM * safe_log(dofk)
                 - 0.5 * (double)DIM / mpk
                 + dga - ds;
        d_Cpart[k] = (float)C;
        d_sdb[k]   = (float)(dgb - ds);
    }
}

// ---------------------------------------------------------------------------
// Packed f32x2 helpers
// ---------------------------------------------------------------------------
static __device__ __forceinline__ unsigned long long ff2(
    unsigned long long a, unsigned long long b, unsigned long long c) {
    unsigned long long d;
    asm("fma.rn.f32x2 %0, %1, %2, %3;" : "=l"(d) : "l"(a), "l"(b), "l"(c));
    return d;
}
static __device__ __forceinline__ unsigned long long fadd2(
    unsigned long long a, unsigned long long b) {
    unsigned long long d;
    asm("add.rn.f32x2 %0, %1, %2;" : "=l"(d) : "l"(a), "l"(b));
    return d;
}
static __device__ __forceinline__ unsigned long long pack2(float x) {
    unsigned long long d;
    asm("mov.b64 %0, {%1, %1};" : "=l"(d) : "f"(x));
    return d;
}
static __device__ __forceinline__ void unpack2(unsigned long long v, float& lo, float& hi) {
    asm("mov.b64 {%0, %1}, %2;" : "=f"(lo), "=f"(hi) : "l"(v));
}

// cp.async 16B helpers
static __device__ __forceinline__ void cp16(uint32_t smem_addr, const void* gptr) {
    asm volatile("cp.async.cg.shared.global [%0], [%1], 16;" :: "r"(smem_addr), "l"(gptr));
}
static __device__ __forceinline__ void cp_commit() {
    asm volatile("cp.async.commit_group;");
}
template <int N>
static __device__ __forceinline__ void cp_wait() {
    asm volatile("cp.async.wait_group %0;" :: "n"(N));
}

// ---------------------------------------------------------------------------
// Main kernel: 256 blocks x 128 threads (4 warps), 128 rows/block, R=4.
// e-EIGHTH SPLIT: warp w computes e-eighths {w, 7-w} (d-work 72 each, all
// warps balanced; triangular bound dmax = 8*(e8+1) — bit-exact zero skip).
// Each P fragment (2 uniform LDS.128 per d) feeds 4 rows x 4 FFMA2 = 16
// FFMA2 -> halves the measured L1-wavefront cost per MAC vs R=2.
// Per-(row,k) sq = sum of 4 warp partials, merged 1-k-deep on the existing
// double-buffer barriers; warp0 owns argmax (strict >, first-max).
// OUTPUT: float32 index values.
// ---------------------------------------------------------------------------
__global__ __launch_bounds__(NTHREADS) void bgm_argmax_kernel(
    const float* __restrict__ X,
    const float* __restrict__ P,
    float* __restrict__ out) {

    extern __shared__ __align__(16) float smem[];
    float* __restrict__ Psm = smem + SM_P;
    float* __restrict__ Xsm = smem + SM_X;
    float* __restrict__ Csm = smem + SM_C;
    float* __restrict__ Sdb = smem + SM_SDB;
    float* __restrict__ SqP = smem + SM_SQP;   // [buf][warp][row]

    const int tid  = threadIdx.x;
    const int wid  = tid >> 5;
    const int lane = tid & 31;
    const int row0 = blockIdx.x * ROWS_PER_BLOCK;

    // Stage X tile: 128 rows -> 2048 float4, 16 per thread (padded rows of 65).
    {
        const float4* __restrict__ Xg =
            reinterpret_cast<const float4*>(X + row0 * DIM);
        for (int i = tid; i < ROWS_PER_BLOCK * (DIM / 4); i += NTHREADS) {
            const float4 v = Xg[i];
            const int r = i >> 4;
            const int c = (i & 15) << 2;
            float* dst = &Xsm[r * 65 + c];
            dst[0] = v.x; dst[1] = v.y; dst[2] = v.z; dst[3] = v.w;
        }
    }
    if (tid < NK) Sdb[tid] = d_sdb[tid];
    __syncthreads();
    if (tid < NK) {   // stick-breaking exclusive cumsum (sequential fp32 order)
        float pre = 0.0f;
        for (int j = 0; j < tid; ++j) pre += Sdb[j];
        Csm[tid] = d_Cpart[tid] + pre;
    }

    // Prologue: stage P_0 into buffer 0 (1024 float4 -> 8 per thread)
    {
        const float4* src = reinterpret_cast<const float4*>(P);
        const uint32_t dst = (uint32_t)__cvta_generic_to_shared(&Psm[0]);
#pragma unroll
        for (int j = 0; j < 8; ++j)
            cp16(dst + (tid + j * NTHREADS) * 16, src + tid + j * NTHREADS);
        cp_commit();
    }

    const int e8A = wid;        // eighths {wid, 7-wid}: d-work 8(w+1)+8(8-w)=72
    const int e8B = 7 - wid;

    int xb[RPT];
#pragma unroll
    for (int r = 0; r < RPT; ++r) xb[r] = (lane + 32 * r) * 65;

    float best[RPT], argf[RPT];
#pragma unroll
    for (int r = 0; r < RPT; ++r) { best[r] = __int_as_float(0xff800000u); argf[r] = 0.0f; }

    const ulonglong2* __restrict__ nmAll =
        reinterpret_cast<const ulonglong2*>(d_negmuP);

    for (int k = 0; k < NK; ++k) {
        __syncthreads();   // (a) prev buffer free; all warps' k-1 partials visible

        // Warp0: merge 4 partials for k-1 and update argmax.
        if (wid == 0 && k > 0) {
            const float* pb = SqP + ((k - 1) & 1) * (4 * ROWS_PER_BLOCK);
            const float Ck = Csm[k - 1];
#pragma unroll
            for (int r = 0; r < RPT; ++r) {
                const int row = lane + 32 * r;
                const float s = (pb[row] + pb[ROWS_PER_BLOCK + row])
                              + (pb[2 * ROWS_PER_BLOCK + row] + pb[3 * ROWS_PER_BLOCK + row]);
                const float w = fmaf(-0.5f, s, Ck);
                if (w > best[r]) { best[r] = w; argf[r] = (float)(k - 1); }
            }
        }

        if (k + 1 < NK) {
            const float4* src = reinterpret_cast<const float4*>(P + (k + 1) * DIM * DIM);
            const uint32_t dst = (uint32_t)__cvta_generic_to_shared(
                &Psm[((k + 1) & 1) * DIM * DIM]);
#pragma unroll
            for (int j = 0; j < 8; ++j)
                cp16(dst + (tid + j * NTHREADS) * 16, src + tid + j * NTHREADS);
            cp_commit();
            cp_wait<1>();   // P_k complete; P_{k+1} in flight
        } else {
            cp_wait<0>();
        }
        __syncthreads();    // (b) P_k visible to all warps

        const float* __restrict__ Pk = &Psm[(k & 1) * DIM * DIM];
        unsigned long long srow[RPT];
#pragma unroll
        for (int r = 0; r < RPT; ++r) srow[r] = 0ULL;

#pragma unroll
        for (int h = 0; h < 2; ++h) {
            const int e8   = (h == 0) ? e8A : e8B;
            const int dmax = 8 * (e8 + 1);       // triangular bound
            const int eoff = e8 << 3;            // e-offset in floats

            unsigned long long acc[RPT][4];
#pragma unroll
            for (int r = 0; r < RPT; ++r)
#pragma unroll
                for (int j = 0; j < 4; ++j) acc[r][j] = 0ULL;

#pragma unroll 4
            for (int d = 0; d < dmax; ++d) {
                const ulonglong2* __restrict__ pr =
                    reinterpret_cast<const ulonglong2*>(Pk + (d << 6) + eoff);
                const ulonglong2 p0 = pr[0];     // 2 uniform LDS.128 = 4 f32x2
                const ulonglong2 p1 = pr[1];
#pragma unroll
                for (int r = 0; r < RPT; ++r) {
                    const unsigned long long xr = pack2(Xsm[xb[r] + d]);
                    acc[r][0] = ff2(xr, p0.x, acc[r][0]);
                    acc[r][1] = ff2(xr, p0.y, acc[r][1]);
                    acc[r][2] = ff2(xr, p1.x, acc[r][2]);
                    acc[r][3] = ff2(xr, p1.y, acc[r][3]);
                }
            }

            // Eighth epilogue: srow += (acc + negmuP_eighth)^2
            const ulonglong2* __restrict__ nm = nmAll + (k << 4) + (e8 << 1);
            const ulonglong2 m0 = nm[0];
            const ulonglong2 m1 = nm[1];
#pragma unroll
            for (int r = 0; r < RPT; ++r) {
                const unsigned long long ea = fadd2(acc[r][0], m0.x);
                const unsigned long long eb = fadd2(acc[r][1], m0.y);
                const unsigned long long ec = fadd2(acc[r][2], m1.x);
                const unsigned long long ed = fadd2(acc[r][3], m1.y);
                srow[r] = ff2(ea, ea, srow[r]);
                srow[r] = ff2(eb, eb, srow[r]);
                srow[r] = ff2(ec, ec, srow[r]);
                srow[r] = ff2(ed, ed, srow[r]);
            }
        }

        // Publish this warp's partials for k.
        float* sp = SqP + (k & 1) * (4 * ROWS_PER_BLOCK) + wid * ROWS_PER_BLOCK;
#pragma unroll
        for (int r = 0; r < RPT; ++r) {
            float lo, hi;
            unpack2(srow[r], lo, hi);
            sp[lane + 32 * r] = lo + hi;
        }
    }

    __syncthreads();   // k=63 partials visible
    if (wid == 0) {
        const float* pb = SqP + ((NK - 1) & 1) * (4 * ROWS_PER_BLOCK);
        const float Ck = Csm[NK - 1];
#pragma unroll
        for (int r = 0; r < RPT; ++r) {
            const int row = lane + 32 * r;
            const float s = (pb[row] + pb[ROWS_PER_BLOCK + row])
                          + (pb[2 * ROWS_PER_BLOCK + row] + pb[3 * ROWS_PER_BLOCK + row]);
            const float w = fmaf(-0.5f, s, Ck);
            if (w > best[r]) { best[r] = w; argf[r] = (float)(NK - 1); }
            out[row0 + row] = argf[r];
        }
    }
}

// ---------------------------------------------------------------------------
// Launch. Inputs identified by ELEMENT COUNT; dof/mp disambiguated on device.
// Output: float32 index values [N].
// ---------------------------------------------------------------------------
extern "C" void kernel_launch(void* const* d_in, const int* in_sizes, int n_in,
                              void* d_out, int out_size) {
    (void)out_size;
    const float* X     = nullptr;
    const float* means = nullptr;
    const float* P     = nullptr;
    const float* wc    = nullptr;
    const float* v64a  = nullptr;
    const float* v64b  = nullptr;

    for (int i = 0; i < n_in; ++i) {
        const float* p = (const float*)d_in[i];
        switch (in_sizes[i]) {
            case 2097152: X = p; break;
            case 262144:  P = p; break;
            case 4096:    means = p; break;
            case 128:     wc = p; break;
            case 64:      if (!v64a) v64a = p; else v64b = p; break;
            default: break;
        }
    }
    if (!v64b) v64b = v64a;  // defensive
    float* out = (float*)d_out;

    static bool attr_set = false;
    if (!attr_set) {
        cudaFuncSetAttribute(bgm_argmax_kernel,
                             cudaFuncAttributeMaxDynamicSharedMemorySize,
                             SMEM_BYTES);
        attr_set = true;
    }

    bgm_prep_a<<<NK, DIM>>>(means, P, wc, v64a, v64b);
    bgm_argmax_kernel<<<NBLOCKS, NTHREADS, SMEM_BYTES>>>(X, P, out);
}